// round 15
// baseline (speedup 1.0000x reference)
#include <cuda_runtime.h>
#include <cuda_fp16.h>
#include <cstdint>

#define TDIM 2048
#define DDIM 64
#define BH 32
#define BQ 128
#define BK 64
#define NTH 128
#define KTILES (TDIM / BK)

// smem layout (bytes): KV double-buffered stages {KH,VH} 8KB each
#define KV_STAGE 16384
#define SMEM_BYTES (2 * KV_STAGE)   // 32 KB -> 2 CTAs/SM

#define NELEM ((size_t)BH * TDIM * DDIM)

__device__ unsigned int g_maskbits[(size_t)TDIM * TDIM / 32];  // 512 KB
__device__ uint4 g_qh[NELEM / 8];
__device__ uint4 g_kh[NELEM / 8];
__device__ uint4 g_vh[NELEM / 8];

// ---------------- helpers ----------------
__device__ __forceinline__ uint32_t smem_u32(const void* p) {
    uint32_t a;
    asm("{ .reg .u64 t; cvta.to.shared.u64 t, %1; cvt.u32.u64 %0, t; }" : "=r"(a) : "l"(p));
    return a;
}
__device__ __forceinline__ uint32_t swz(uint32_t byte) {
    return byte ^ ((byte >> 3) & 0x70);
}
__device__ __forceinline__ void cp16(uint32_t dst, const void* src) {
    asm volatile("cp.async.cg.shared.global [%0], [%1], 16;" :: "r"(dst), "l"(src));
}
#define CP_COMMIT() asm volatile("cp.async.commit_group;" ::: "memory")
#define CP_WAIT(n)  asm volatile("cp.async.wait_group %0;" :: "n"(n) : "memory")

__device__ __forceinline__ void ldsm_x4(uint32_t (&r)[4], uint32_t addr) {
    asm volatile("ldmatrix.sync.aligned.m8n8.x4.shared.b16 {%0,%1,%2,%3}, [%4];"
                 : "=r"(r[0]), "=r"(r[1]), "=r"(r[2]), "=r"(r[3]) : "r"(addr));
}
__device__ __forceinline__ void ldsm_x4_t(uint32_t (&r)[4], uint32_t addr) {
    asm volatile("ldmatrix.sync.aligned.m8n8.x4.trans.shared.b16 {%0,%1,%2,%3}, [%4];"
                 : "=r"(r[0]), "=r"(r[1]), "=r"(r[2]), "=r"(r[3]) : "r"(addr));
}
// fp16 MMA, fp32 accumulate
__device__ __forceinline__ void mma16816(float (&c)[4], const uint32_t (&a)[4],
                                         uint32_t b0, uint32_t b1) {
    asm volatile(
        "mma.sync.aligned.m16n8k16.row.col.f32.f16.f16.f32 "
        "{%0,%1,%2,%3}, {%4,%5,%6,%7}, {%8,%9}, {%0,%1,%2,%3};"
        : "+f"(c[0]), "+f"(c[1]), "+f"(c[2]), "+f"(c[3])
        : "r"(a[0]), "r"(a[1]), "r"(a[2]), "r"(a[3]), "r"(b0), "r"(b1));
}
__device__ __forceinline__ float ex2f(float x) {
    float r;
    asm("ex2.approx.f32 %0, %1;" : "=f"(r) : "f"(x));
    return r;
}
// pack two fp32 into fp16x2 (lo=x, hi=y) — single CVT
__device__ __forceinline__ uint32_t pack_h2(float x, float y) {
    uint32_t r;
    asm("cvt.rn.f16x2.f32 %0, %1, %2;" : "=r"(r) : "f"(y), "f"(x));
    return r;
}

// ---------------- prepass kernels ----------------
__global__ void pack_mask(const int* __restrict__ m) {
    int w = blockIdx.x * blockDim.x + threadIdx.x;
    if (w >= (TDIM * TDIM) / 32) return;
    const int4* p = (const int4*)(m + (size_t)w * 32);
    unsigned int bits = 0;
    #pragma unroll
    for (int i = 0; i < 8; ++i) {
        int4 v = p[i];
        bits |= (unsigned)(v.x != 0) << (i * 4);
        bits |= (unsigned)(v.y != 0) << (i * 4 + 1);
        bits |= (unsigned)(v.z != 0) << (i * 4 + 2);
        bits |= (unsigned)(v.w != 0) << (i * 4 + 3);
    }
    g_maskbits[w] = bits;
}

// fp32 -> fp16 (8 elems/thread), with scale
__global__ void cvt_f16(const float4* __restrict__ src, uint4* __restrict__ dst,
                        float scale, int n16) {
    int i = blockIdx.x * blockDim.x + threadIdx.x;
    if (i >= n16) return;
    float4 a = src[2 * i], b = src[2 * i + 1];
    uint4 w;
    w.x = pack_h2(a.x * scale, a.y * scale);
    w.y = pack_h2(a.z * scale, a.w * scale);
    w.z = pack_h2(b.x * scale, b.y * scale);
    w.w = pack_h2(b.z * scale, b.w * scale);
    dst[i] = w;
}

// -------- main kernel: 4 warps x 32 rows, B-frag reuse x2, 2 CTAs/SM --------
__global__ __launch_bounds__(NTH, 2)
void fa_mma(float* __restrict__ go)
{
    extern __shared__ char smem[];
    const uint32_t sb = smem_u32(smem);
    const int tid = threadIdx.x;
    const int lane = tid & 31, wid = tid >> 5;
    const int bh = blockIdx.y;
    const int q0 = blockIdx.x * BQ;
    const int m0 = wid * 32;          // warp owns 32 rows (two 16-row blocks)

    const size_t row_bytes = 128;
    const char* gqh = (const char*)g_qh + ((size_t)bh * TDIM + q0) * row_bytes;
    const char* gkh0 = (const char*)g_kh + (size_t)bh * TDIM * row_bytes;
    const char* gvh0 = (const char*)g_vh + (size_t)bh * TDIM * row_bytes;
    float* ob = go + (size_t)bh * TDIM * DDIM;

    // ---- K/V tile 0 into stage 0 (8 cp16/thread: KH, VH) ----
    #pragma unroll
    for (int j = 0; j < 4; ++j) {
        uint32_t byte = (tid + j * NTH) * 16;
        uint32_t sw = swz(byte);
        cp16(sb + sw,        gkh0 + byte);
        cp16(sb + 8192 + sw, gvh0 + byte);
    }
    CP_COMMIT();

    const int g  = lane >> 2;
    const int tq = lane & 3;

    // ---- Q fragments for both row-blocks straight from global ----
    uint32_t aQ[2][4][4];
    #pragma unroll
    for (int rb = 0; rb < 2; ++rb) {
        int r0 = m0 + rb * 16 + g;
        #pragma unroll
        for (int ks = 0; ks < 4; ++ks) {
            uint32_t cb = ks * 32 + tq * 4;
            const char* r0h = gqh + (size_t)r0 * 128;
            const char* r1h = gqh + (size_t)(r0 + 8) * 128;
            aQ[rb][ks][0] = *(const uint32_t*)(r0h + cb);
            aQ[rb][ks][1] = *(const uint32_t*)(r1h + cb);
            aQ[rb][ks][2] = *(const uint32_t*)(r0h + cb + 16);
            aQ[rb][ks][3] = *(const uint32_t*)(r1h + cb + 16);
        }
    }

    // fragment address pieces (B operands via ldmatrix)
    const uint32_t brow  = ((lane >> 4) & 1) * 8 + (lane & 7);
    const uint32_t bcol0 = ((lane >> 3) & 1) * 16;
    const uint32_t trow0 = ((lane >> 3) & 1) * 8 + (lane & 7);
    const uint32_t tcol0 = ((lane >> 4) & 1) * 16;

    float oreg[2][8][4];
    #pragma unroll
    for (int rb = 0; rb < 2; ++rb)
        #pragma unroll
        for (int i = 0; i < 8; ++i)
            #pragma unroll
            for (int j = 0; j < 4; ++j) oreg[rb][i][j] = 0.f;
    float lsum[2][2] = {{0.f, 0.f}, {0.f, 0.f}};

    CP_WAIT(0);
    __syncthreads();

    for (int kt = 0; kt < KTILES; ++kt) {
        // ---- prefetch next tile into alternate stage ----
        if (kt + 1 < KTILES) {
            const size_t toff = (size_t)(kt + 1) * BK * row_bytes;
            uint32_t base = sb + ((kt + 1) & 1) * KV_STAGE;
            #pragma unroll
            for (int j = 0; j < 4; ++j) {
                uint32_t byte = (tid + j * NTH) * 16;
                uint32_t sw = swz(byte);
                cp16(base + sw,        gkh0 + toff + byte);
                cp16(base + 8192 + sw, gvh0 + toff + byte);
            }
            CP_COMMIT();
        }

        const uint32_t kvb = sb + (kt & 1) * KV_STAGE;
        const uint32_t khb = kvb, vhb = kvb + 8192;

        // ---- S = Q K^T for both row-blocks (B-frag loaded once, used twice) ----
        float s[2][8][4];
        #pragma unroll
        for (int rb = 0; rb < 2; ++rb)
            #pragma unroll
            for (int i = 0; i < 8; ++i)
                #pragma unroll
                for (int j = 0; j < 4; ++j) s[rb][i][j] = 0.f;

        #pragma unroll
        for (int ks = 0; ks < 4; ++ks) {
            #pragma unroll
            for (int np = 0; np < 4; ++np) {
                uint32_t sw = swz((np * 16 + brow) * 128 + ks * 32 + bcol0);
                uint32_t bHf[4];
                ldsm_x4(bHf, khb + sw);
                #pragma unroll
                for (int rb = 0; rb < 2; ++rb) {
                    mma16816(s[rb][2 * np],     aQ[rb][ks], bHf[0], bHf[1]);
                    mma16816(s[rb][2 * np + 1], aQ[rb][ks], bHf[2], bHf[3]);
                }
            }
        }

        // ---- mask + exp2 -> register-resident P for both row-blocks ----
        uint32_t aP[2][4][4];
        #pragma unroll
        for (int rb = 0; rb < 2; ++rb) {
            int r0 = m0 + rb * 16 + g;
            unsigned long long mw0 =
                *(const unsigned long long*)(g_maskbits + (size_t)(q0 + r0) * (TDIM / 32) + kt * 2);
            unsigned long long mw1 =
                *(const unsigned long long*)(g_maskbits + (size_t)(q0 + r0 + 8) * (TDIM / 32) + kt * 2);
            #pragma unroll
            for (int ks = 0; ks < 4; ++ks) {
                #pragma unroll
                for (int h = 0; h < 2; ++h) {          // n8-tile 2ks+h
                    int ng = 2 * ks + h;
                    int c = ng * 8 + tq * 2;
                    float p0 = ((mw0 >> c) & 1ULL)       ? 0.f : ex2f(s[rb][ng][0]);
                    float p1 = ((mw0 >> (c + 1)) & 1ULL) ? 0.f : ex2f(s[rb][ng][1]);
                    float p2 = ((mw1 >> c) & 1ULL)       ? 0.f : ex2f(s[rb][ng][2]);
                    float p3 = ((mw1 >> (c + 1)) & 1ULL) ? 0.f : ex2f(s[rb][ng][3]);
                    lsum[rb][0] += p0 + p1;
                    lsum[rb][1] += p2 + p3;
                    aP[rb][ks][2 * h]     = pack_h2(p0, p1);   // row g
                    aP[rb][ks][2 * h + 1] = pack_h2(p2, p3);   // row g+8
                }
            }
        }

        // ---- O += P V for both row-blocks (V-frag loaded once, used twice) ----
        #pragma unroll
        for (int ks = 0; ks < 4; ++ks) {
            #pragma unroll
            for (int np = 0; np < 4; ++np) {
                uint32_t swB = swz((ks * 16 + trow0) * 128 + np * 32 + tcol0);
                uint32_t bVf[4];
                ldsm_x4_t(bVf, vhb + swB);
                #pragma unroll
                for (int rb = 0; rb < 2; ++rb) {
                    mma16816(oreg[rb][2 * np],     aP[rb][ks], bVf[0], bVf[1]);
                    mma16816(oreg[rb][2 * np + 1], aP[rb][ks], bVf[2], bVf[3]);
                }
            }
        }

        // next tile resident + everyone done with this stage
        if (kt + 1 < KTILES) CP_WAIT(0);
        __syncthreads();
    }

    // ---- epilogue ----
    #pragma unroll
    for (int rb = 0; rb < 2; ++rb) {
        #pragma unroll
        for (int off = 1; off <= 2; off <<= 1) {
            lsum[rb][0] += __shfl_xor_sync(0xffffffffu, lsum[rb][0], off);
            lsum[rb][1] += __shfl_xor_sync(0xffffffffu, lsum[rb][1], off);
        }
        float inv0 = 1.f / lsum[rb][0];
        float inv1 = 1.f / lsum[rb][1];
        int r0 = m0 + rb * 16 + g;
        float* orow0 = ob + (size_t)(q0 + r0) * DDIM;
        float* orow1 = ob + (size_t)(q0 + r0 + 8) * DDIM;
        #pragma unroll
        for (int ng = 0; ng < 8; ++ng) {
            int c = ng * 8 + tq * 2;
            *(float2*)(orow0 + c) = make_float2(oreg[rb][ng][0] * inv0, oreg[rb][ng][1] * inv0);
            *(float2*)(orow1 + c) = make_float2(oreg[rb][ng][2] * inv1, oreg[rb][ng][3] * inv1);
        }
    }
}

extern "C" void kernel_launch(void* const* d_in, const int* in_sizes, int n_in,
                              void* d_out, int out_size) {
    const float* q = (const float*)d_in[0];
    const float* k = (const float*)d_in[1];
    const float* v = (const float*)d_in[2];
    const int* mask = (const int*)d_in[3];
    float* out = (float*)d_out;

    uint4 *qh, *kh, *vh;
    cudaGetSymbolAddress((void**)&qh, g_qh);
    cudaGetSymbolAddress((void**)&kh, g_kh);
    cudaGetSymbolAddress((void**)&vh, g_vh);

    pack_mask<<<(TDIM * TDIM / 32 + 255) / 256, 256>>>(mask);

    const int n16 = (int)(NELEM / 8);
    // Q scale folds softmax 1/sqrt(D) and log2(e): exp(s) == exp2(s*log2e)
    const float qscale = 0.125f * 1.44269504088896340736f;
    cvt_f16<<<(n16 + 255) / 256, 256>>>((const float4*)q, qh, qscale, n16);
    cvt_f16<<<(n16 + 255) / 256, 256>>>((const float4*)k, kh, 1.0f, n16);
    cvt_f16<<<(n16 + 255) / 256, 256>>>((const float4*)v, vh, 1.0f, n16);

    cudaFuncSetAttribute(fa_mma, cudaFuncAttributeMaxDynamicSharedMemorySize, SMEM_BYTES);
    dim3 grid(TDIM / BQ, BH);
    fa_mma<<<grid, NTH, SMEM_BYTES>>>(out);
}

// round 16
// speedup vs baseline: 1.4364x; 1.4364x over previous
#include <cuda_runtime.h>
#include <cuda_fp16.h>
#include <cstdint>

#define TDIM 2048
#define DDIM 64
#define BH 32
#define BQ 64
#define BK 64
#define NTH 128
#define KTILES (TDIM / BK)

// smem layout (bytes): KV double-buffered stages {KH,VH} 8KB each
#define KV_STAGE 16384
#define SMEM_BYTES (2 * KV_STAGE)   // 32 KB -> 4 CTAs/SM

#define NELEM ((size_t)BH * TDIM * DDIM)

__device__ unsigned int g_maskbits[(size_t)TDIM * TDIM / 32];  // 512 KB
__device__ uint4 g_qh[NELEM / 8];
__device__ uint4 g_kh[NELEM / 8];
__device__ uint4 g_vh[NELEM / 8];

// ---------------- helpers ----------------
__device__ __forceinline__ uint32_t smem_u32(const void* p) {
    uint32_t a;
    asm("{ .reg .u64 t; cvta.to.shared.u64 t, %1; cvt.u32.u64 %0, t; }" : "=r"(a) : "l"(p));
    return a;
}
__device__ __forceinline__ uint32_t swz(uint32_t byte) {
    return byte ^ ((byte >> 3) & 0x70);
}
__device__ __forceinline__ void cp16(uint32_t dst, const void* src) {
    asm volatile("cp.async.cg.shared.global [%0], [%1], 16;" :: "r"(dst), "l"(src));
}
#define CP_COMMIT() asm volatile("cp.async.commit_group;" ::: "memory")
#define CP_WAIT(n)  asm volatile("cp.async.wait_group %0;" :: "n"(n) : "memory")

__device__ __forceinline__ void ldsm_x4(uint32_t (&r)[4], uint32_t addr) {
    asm volatile("ldmatrix.sync.aligned.m8n8.x4.shared.b16 {%0,%1,%2,%3}, [%4];"
                 : "=r"(r[0]), "=r"(r[1]), "=r"(r[2]), "=r"(r[3]) : "r"(addr));
}
__device__ __forceinline__ void ldsm_x4_t(uint32_t (&r)[4], uint32_t addr) {
    asm volatile("ldmatrix.sync.aligned.m8n8.x4.trans.shared.b16 {%0,%1,%2,%3}, [%4];"
                 : "=r"(r[0]), "=r"(r[1]), "=r"(r[2]), "=r"(r[3]) : "r"(addr));
}
// fp16 MMA, fp32 accumulate
__device__ __forceinline__ void mma16816(float (&c)[4], const uint32_t (&a)[4],
                                         uint32_t b0, uint32_t b1) {
    asm volatile(
        "mma.sync.aligned.m16n8k16.row.col.f32.f16.f16.f32 "
        "{%0,%1,%2,%3}, {%4,%5,%6,%7}, {%8,%9}, {%0,%1,%2,%3};"
        : "+f"(c[0]), "+f"(c[1]), "+f"(c[2]), "+f"(c[3])
        : "r"(a[0]), "r"(a[1]), "r"(a[2]), "r"(a[3]), "r"(b0), "r"(b1));
}
// packed fp16x2 exp2
__device__ __forceinline__ uint32_t ex2_h2(uint32_t x) {
    uint32_t r;
    asm("ex2.approx.f16x2 %0, %1;" : "=r"(r) : "r"(x));
    return r;
}
// pack two fp32 into fp16x2 (lo=x, hi=y) — single CVT
__device__ __forceinline__ uint32_t pack_h2(float x, float y) {
    uint32_t r;
    asm("cvt.rn.f16x2.f32 %0, %1, %2;" : "=r"(r) : "f"(y), "f"(x));
    return r;
}

// ---------------- prepass kernels ----------------
__global__ void pack_mask(const int* __restrict__ m) {
    int w = blockIdx.x * blockDim.x + threadIdx.x;
    if (w >= (TDIM * TDIM) / 32) return;
    const int4* p = (const int4*)(m + (size_t)w * 32);
    unsigned int bits = 0;
    #pragma unroll
    for (int i = 0; i < 8; ++i) {
        int4 v = p[i];
        bits |= (unsigned)(v.x != 0) << (i * 4);
        bits |= (unsigned)(v.y != 0) << (i * 4 + 1);
        bits |= (unsigned)(v.z != 0) << (i * 4 + 2);
        bits |= (unsigned)(v.w != 0) << (i * 4 + 3);
    }
    g_maskbits[w] = bits;
}

// fp32 -> fp16 (8 elems/thread), with scale
__global__ void cvt_f16(const float4* __restrict__ src, uint4* __restrict__ dst,
                        float scale, int n16) {
    int i = blockIdx.x * blockDim.x + threadIdx.x;
    if (i >= n16) return;
    float4 a = src[2 * i], b = src[2 * i + 1];
    uint4 w;
    w.x = pack_h2(a.x * scale, a.y * scale);
    w.y = pack_h2(a.z * scale, a.w * scale);
    w.z = pack_h2(b.x * scale, b.y * scale);
    w.w = pack_h2(b.z * scale, b.w * scale);
    dst[i] = w;
}

// -------- main kernel: 4 warps/CTA, fp16 softmax, ones-MMA lsum, 4 CTAs/SM --------
__global__ __launch_bounds__(NTH, 4)
void fa_mma(float* __restrict__ go)
{
    extern __shared__ char smem[];
    const uint32_t sb = smem_u32(smem);
    const int tid = threadIdx.x;
    const int lane = tid & 31, wid = tid >> 5;
    const int bh = blockIdx.y;
    const int q0 = blockIdx.x * BQ;
    const int m0 = wid * 16;

    const size_t row_bytes = 128;
    const char* gqh = (const char*)g_qh + ((size_t)bh * TDIM + q0) * row_bytes;
    const char* gkh0 = (const char*)g_kh + (size_t)bh * TDIM * row_bytes;
    const char* gvh0 = (const char*)g_vh + (size_t)bh * TDIM * row_bytes;
    float* ob = go + (size_t)bh * TDIM * DDIM;

    // ---- K/V tile 0 into stage 0 (8 cp16/thread: KH, VH) ----
    #pragma unroll
    for (int j = 0; j < 4; ++j) {
        uint32_t byte = (tid + j * NTH) * 16;
        uint32_t sw = swz(byte);
        cp16(sb + sw,        gkh0 + byte);
        cp16(sb + 8192 + sw, gvh0 + byte);
    }
    CP_COMMIT();

    const int g  = lane >> 2;
    const int tq = lane & 3;
    const int r0loc = m0 + g;

    // ---- Q fragments straight from global (A-frag = 2 consecutive fp16) ----
    uint32_t aQ[4][4];
    #pragma unroll
    for (int ks = 0; ks < 4; ++ks) {
        uint32_t cb = ks * 32 + tq * 4;
        const char* r0h = gqh + (size_t)r0loc * 128;
        const char* r1h = gqh + (size_t)(r0loc + 8) * 128;
        aQ[ks][0] = *(const uint32_t*)(r0h + cb);
        aQ[ks][1] = *(const uint32_t*)(r1h + cb);
        aQ[ks][2] = *(const uint32_t*)(r0h + cb + 16);
        aQ[ks][3] = *(const uint32_t*)(r1h + cb + 16);
    }

    // fragment address pieces (B operands via ldmatrix)
    const uint32_t brow  = ((lane >> 4) & 1) * 8 + (lane & 7);
    const uint32_t bcol0 = ((lane >> 3) & 1) * 16;
    const uint32_t trow0 = ((lane >> 3) & 1) * 8 + (lane & 7);
    const uint32_t tcol0 = ((lane >> 4) & 1) * 16;

    float oreg[8][4];
    #pragma unroll
    for (int i = 0; i < 8; ++i)
        #pragma unroll
        for (int j = 0; j < 4; ++j) oreg[i][j] = 0.f;
    float lreg[4] = {0.f, 0.f, 0.f, 0.f};     // row sums via ones-MMA
    const uint32_t ONES = 0x3C003C00u;         // (1.0h, 1.0h)

    CP_WAIT(0);
    __syncthreads();

    for (int kt = 0; kt < KTILES; ++kt) {
        // ---- prefetch next tile into alternate stage ----
        if (kt + 1 < KTILES) {
            const size_t toff = (size_t)(kt + 1) * BK * row_bytes;
            uint32_t base = sb + ((kt + 1) & 1) * KV_STAGE;
            #pragma unroll
            for (int j = 0; j < 4; ++j) {
                uint32_t byte = (tid + j * NTH) * 16;
                uint32_t sw = swz(byte);
                cp16(base + sw,        gkh0 + toff + byte);
                cp16(base + 8192 + sw, gvh0 + toff + byte);
            }
            CP_COMMIT();
        }

        // early mask fetch
        unsigned long long mw0 =
            *(const unsigned long long*)(g_maskbits + (size_t)(q0 + r0loc) * (TDIM / 32) + kt * 2);
        unsigned long long mw1 =
            *(const unsigned long long*)(g_maskbits + (size_t)(q0 + r0loc + 8) * (TDIM / 32) + kt * 2);

        const uint32_t kvb = sb + (kt & 1) * KV_STAGE;
        const uint32_t khb = kvb, vhb = kvb + 8192;

        // ---- S = Q K^T (single-term fp16) ----
        float s[8][4];
        #pragma unroll
        for (int i = 0; i < 8; ++i)
            #pragma unroll
            for (int j = 0; j < 4; ++j) s[i][j] = 0.f;

        #pragma unroll
        for (int ks = 0; ks < 4; ++ks) {
            #pragma unroll
            for (int np = 0; np < 4; ++np) {
                uint32_t sw = swz((np * 16 + brow) * 128 + ks * 32 + bcol0);
                uint32_t bHf[4];
                ldsm_x4(bHf, khb + sw);
                mma16816(s[2 * np],     aQ[ks], bHf[0], bHf[1]);
                mma16816(s[2 * np + 1], aQ[ks], bHf[2], bHf[3]);
            }
        }

        // ---- mask (pre-exp, fp32) -> pack fp16x2 -> ex2.f16x2 = P A-frags ----
        uint32_t aP[4][4];
        #pragma unroll
        for (int ks = 0; ks < 4; ++ks) {
            #pragma unroll
            for (int h = 0; h < 2; ++h) {          // n8-tile 2ks+h
                int ng = 2 * ks + h;
                int c = ng * 8 + tq * 2;
                float s0 = ((mw0 >> c) & 1ULL)       ? -30000.f : s[ng][0];
                float s1 = ((mw0 >> (c + 1)) & 1ULL) ? -30000.f : s[ng][1];
                float s2 = ((mw1 >> c) & 1ULL)       ? -30000.f : s[ng][2];
                float s3 = ((mw1 >> (c + 1)) & 1ULL) ? -30000.f : s[ng][3];
                aP[ks][2 * h]     = ex2_h2(pack_h2(s0, s1));   // row g
                aP[ks][2 * h + 1] = ex2_h2(pack_h2(s2, s3));   // row g+8
            }
        }

        // ---- O += P V (fp16), V via ldmatrix.trans; lsum via ones-MMA ----
        #pragma unroll
        for (int ks = 0; ks < 4; ++ks) {
            mma16816(lreg, aP[ks], ONES, ONES);   // row sums (exact fp32 reduce)
            #pragma unroll
            for (int np = 0; np < 4; ++np) {
                uint32_t swB = swz((ks * 16 + trow0) * 128 + np * 32 + tcol0);
                uint32_t bVf[4];
                ldsm_x4_t(bVf, vhb + swB);
                mma16816(oreg[2 * np],     aP[ks], bVf[0], bVf[1]);
                mma16816(oreg[2 * np + 1], aP[ks], bVf[2], bVf[3]);
            }
        }

        // next tile resident + everyone done with this stage
        if (kt + 1 < KTILES) CP_WAIT(0);
        __syncthreads();
    }

    // ---- epilogue: lreg[0]/lreg[2] are complete row sums (no shuffle) ----
    float inv0 = 1.f / lreg[0];
    float inv1 = 1.f / lreg[2];

    float* orow0 = ob + (size_t)(q0 + r0loc) * DDIM;
    float* orow1 = ob + (size_t)(q0 + r0loc + 8) * DDIM;
    #pragma unroll
    for (int ng = 0; ng < 8; ++ng) {
        int c = ng * 8 + tq * 2;
        *(float2*)(orow0 + c) = make_float2(oreg[ng][0] * inv0, oreg[ng][1] * inv0);
        *(float2*)(orow1 + c) = make_float2(oreg[ng][2] * inv1, oreg[ng][3] * inv1);
    }
}

extern "C" void kernel_launch(void* const* d_in, const int* in_sizes, int n_in,
                              void* d_out, int out_size) {
    const float* q = (const float*)d_in[0];
    const float* k = (const float*)d_in[1];
    const float* v = (const float*)d_in[2];
    const int* mask = (const int*)d_in[3];
    float* out = (float*)d_out;

    uint4 *qh, *kh, *vh;
    cudaGetSymbolAddress((void**)&qh, g_qh);
    cudaGetSymbolAddress((void**)&kh, g_kh);
    cudaGetSymbolAddress((void**)&vh, g_vh);

    pack_mask<<<(TDIM * TDIM / 32 + 255) / 256, 256>>>(mask);

    const int n16 = (int)(NELEM / 8);
    // Q scale folds softmax 1/sqrt(D) and log2(e): exp(s) == exp2(s*log2e)
    const float qscale = 0.125f * 1.44269504088896340736f;
    cvt_f16<<<(n16 + 255) / 256, 256>>>((const float4*)q, qh, qscale, n16);
    cvt_f16<<<(n16 + 255) / 256, 256>>>((const float4*)k, kh, 1.0f, n16);
    cvt_f16<<<(n16 + 255) / 256, 256>>>((const float4*)v, vh, 1.0f, n16);

    cudaFuncSetAttribute(fa_mma, cudaFuncAttributeMaxDynamicSharedMemorySize, SMEM_BYTES);
    dim3 grid(TDIM / BQ, BH);
    fa_mma<<<grid, NTH, SMEM_BYTES>>>(out);
}